// round 1
// baseline (speedup 1.0000x reference)
#include <cuda_runtime.h>
#include <cuda_bf16.h>
#include <cstdint>

// Problem constants (shape-fixed problem: N=20000, K=32, C=512, OUT=512)
#define C_DIM   512
#define OUT_DIM 512
#define K_NB    32
#define N_MAX   20000

// GEMM tiling
#define BM 128
#define BN 128
#define BK 32
#define SSTR 36            // smem row stride in floats (pad 32 -> 36, conflict-free frags)
#define NTHREADS 256

// Scratch for agg = mean(neigh_x) : [N, C] fp32
__device__ float g_agg[(size_t)N_MAX * C_DIM];

// ---------------------------------------------------------------------------
// Kernel 1: mean over neighbor axis.  neigh_x: [N, K, C] row-major.
// One block per node, 128 threads, each thread owns one float4 of C.
// ---------------------------------------------------------------------------
__global__ void __launch_bounds__(128) mean_kernel(const float* __restrict__ nx, int N)
{
    int n  = blockIdx.x;
    int c4 = threadIdx.x;                          // 0..127
    const float4* p = reinterpret_cast<const float4*>(nx + (size_t)n * K_NB * C_DIM) + c4;
    float4 s = make_float4(0.f, 0.f, 0.f, 0.f);
#pragma unroll 8
    for (int k = 0; k < K_NB; ++k) {
        float4 v = p[(size_t)k * (C_DIM / 4)];
        s.x += v.x; s.y += v.y; s.z += v.z; s.w += v.w;
    }
    const float inv = 1.0f / (float)K_NB;
    s.x *= inv; s.y *= inv; s.z *= inv; s.w *= inv;
    reinterpret_cast<float4*>(g_agg + (size_t)n * C_DIM)[c4] = s;
}

// ---------------------------------------------------------------------------
// Kernel 2: out = x @ W_l^T + agg @ W_r^T + (b_l + b_r)
// tf32 mma.sync m16n8k8, fp32 accumulate. Concatenated K = 1024 handled as
// 32 k-tiles of 32: tiles 0..15 use (x, W_l), tiles 16..31 use (agg, W_r).
// Block tile 128x128, 8 warps of 32x64, cp.async double-buffered smem.
// ---------------------------------------------------------------------------
__device__ __forceinline__ uint32_t f2tf32(float f) {
    uint32_t r;
    asm("cvt.rna.tf32.f32 %0, %1;" : "=r"(r) : "f"(f));
    return r;
}

__device__ __forceinline__ void mma_tf32(float* c, const uint32_t* a, const uint32_t* b) {
    asm volatile(
        "mma.sync.aligned.m16n8k8.row.col.f32.tf32.tf32.f32 "
        "{%0,%1,%2,%3}, {%4,%5,%6,%7}, {%8,%9}, {%0,%1,%2,%3};"
        : "+f"(c[0]), "+f"(c[1]), "+f"(c[2]), "+f"(c[3])
        : "r"(a[0]), "r"(a[1]), "r"(a[2]), "r"(a[3]), "r"(b[0]), "r"(b[1]));
}

__device__ __forceinline__ void cp_async16(void* smem_dst, const void* gmem_src, int src_bytes) {
    uint32_t saddr = (uint32_t)__cvta_generic_to_shared(smem_dst);
    asm volatile("cp.async.cg.shared.global [%0], [%1], 16, %2;\n"
                 :: "r"(saddr), "l"(gmem_src), "r"(src_bytes));
}
__device__ __forceinline__ void cp_async_commit() { asm volatile("cp.async.commit_group;\n"); }
__device__ __forceinline__ void cp_async_wait0()  { asm volatile("cp.async.wait_group 0;\n"); }
__device__ __forceinline__ void cp_async_wait1()  { asm volatile("cp.async.wait_group 1;\n"); }

__global__ void __launch_bounds__(NTHREADS, 2)
gemm_kernel(const float* __restrict__ x,
            const float* __restrict__ Wl,
            const float* __restrict__ Wr,
            const float* __restrict__ bl,
            const float* __restrict__ br,
            float* __restrict__ out,
            int Nrows)
{
    extern __shared__ float smem[];
    float* As = smem;                      // 2 stages * BM * SSTR
    float* Bs = smem + 2 * BM * SSTR;      // 2 stages * BN * SSTR

    const int tid  = threadIdx.x;
    const int lane = tid & 31;
    const int warp = tid >> 5;
    const int wm   = warp & 3;             // 0..3 -> 32-row strip
    const int wn   = warp >> 2;            // 0..1 -> 64-col strip

    const int blockRow = blockIdx.y * BM;
    const int blockCol = blockIdx.x * BN;

    float acc[2][8][4];
#pragma unroll
    for (int mt = 0; mt < 2; ++mt)
#pragma unroll
        for (int nt = 0; nt < 8; ++nt)
#pragma unroll
            for (int i = 0; i < 4; ++i) acc[mt][nt][i] = 0.f;

    const int NTILES = 32;   // 2 sources * 16 ktiles of 32

    // ---- tile loader ----
    auto issue_tile = [&](int t, int stage) {
        const int   src = t >> 4;
        const int   kt  = (t & 15) * BK;
        const float* Ap = src ? g_agg : x;
        const float* Bp = src ? Wr    : Wl;
        float* as = As + stage * BM * SSTR;
        float* bs = Bs + stage * BN * SSTR;
#pragma unroll
        for (int i = 0; i < 4; ++i) {
            int idx = i * NTHREADS + tid;      // 0..1023
            int r   = idx >> 3;                // 0..127
            int c   = (idx & 7) * 4;           // 0..28
            // A tile (rows of x/agg) -- guard OOB rows with zero-fill
            int grow = blockRow + r;
            const float* gA = Ap + (size_t)grow * C_DIM + kt + c;
            cp_async16(as + r * SSTR + c, gA, (grow < Nrows) ? 16 : 0);
            // B tile (rows = out channels) -- OUT divisible by BN, no guard
            int go = blockCol + r;
            const float* gB = Bp + (size_t)go * C_DIM + kt + c;
            cp_async16(bs + r * SSTR + c, gB, 16);
        }
        cp_async_commit();
    };

    // ---- tile compute ----
    auto compute_tile = [&](int stage) {
        const float* as = As + stage * BM * SSTR;
        const float* bs = Bs + stage * BN * SSTR;
#pragma unroll
        for (int ks = 0; ks < 4; ++ks) {
            const int kb = ks * 8;
            uint32_t afr[2][4];
#pragma unroll
            for (int mt = 0; mt < 2; ++mt) {
                int row = wm * 32 + mt * 16 + (lane >> 2);
                int col = kb + (lane & 3);
                afr[mt][0] = f2tf32(as[row * SSTR + col]);
                afr[mt][1] = f2tf32(as[(row + 8) * SSTR + col]);
                afr[mt][2] = f2tf32(as[row * SSTR + col + 4]);
                afr[mt][3] = f2tf32(as[(row + 8) * SSTR + col + 4]);
            }
            uint32_t bfr[8][2];
#pragma unroll
            for (int nt = 0; nt < 8; ++nt) {
                int o = wn * 64 + nt * 8 + (lane >> 2);
                int k = kb + (lane & 3);
                bfr[nt][0] = f2tf32(bs[o * SSTR + k]);
                bfr[nt][1] = f2tf32(bs[o * SSTR + k + 4]);
            }
#pragma unroll
            for (int mt = 0; mt < 2; ++mt)
#pragma unroll
                for (int nt = 0; nt < 8; ++nt)
                    mma_tf32(acc[mt][nt], afr[mt], bfr[nt]);
        }
    };

    // ---- pipelined mainloop ----
    issue_tile(0, 0);
    for (int t = 0; t < NTILES; ++t) {
        if (t + 1 < NTILES) {
            issue_tile(t + 1, (t + 1) & 1);
            cp_async_wait1();          // wait for tile t, allow prefetch t+1 in flight
        } else {
            cp_async_wait0();
        }
        __syncthreads();
        compute_tile(t & 1);
        __syncthreads();               // protect buffer reuse by next issue
    }

    // ---- epilogue: add fused bias, store fp32 ----
#pragma unroll
    for (int nt = 0; nt < 8; ++nt) {
        int col = blockCol + wn * 64 + nt * 8 + 2 * (lane & 3);
        float bias0 = bl[col]     + br[col];
        float bias1 = bl[col + 1] + br[col + 1];
#pragma unroll
        for (int mt = 0; mt < 2; ++mt) {
            int row0 = blockRow + wm * 32 + mt * 16 + (lane >> 2);
            int row1 = row0 + 8;
            if (row0 < Nrows) {
                float2 v = make_float2(acc[mt][nt][0] + bias0, acc[mt][nt][1] + bias1);
                *reinterpret_cast<float2*>(out + (size_t)row0 * OUT_DIM + col) = v;
            }
            if (row1 < Nrows) {
                float2 v = make_float2(acc[mt][nt][2] + bias0, acc[mt][nt][3] + bias1);
                *reinterpret_cast<float2*>(out + (size_t)row1 * OUT_DIM + col) = v;
            }
        }
    }
}

// ---------------------------------------------------------------------------
// Launch
// Inputs: x[N,C], neigh_x[N,K,C], W_l[OUT,C], b_l[OUT], W_r[OUT,C], b_r[OUT]
// Output: out[N,OUT] fp32
// ---------------------------------------------------------------------------
extern "C" void kernel_launch(void* const* d_in, const int* in_sizes, int n_in,
                              void* d_out, int out_size)
{
    const float* x     = (const float*)d_in[0];
    const float* neigh = (const float*)d_in[1];
    const float* Wl    = (const float*)d_in[2];
    const float* bl    = (const float*)d_in[3];
    const float* Wr    = (const float*)d_in[4];
    const float* br    = (const float*)d_in[5];
    float* out = (float*)d_out;

    const int N = in_sizes[0] / C_DIM;   // 20000

    // Kernel 1: neighbor mean -> g_agg
    mean_kernel<<<N, 128>>>(neigh, N);

    // Kernel 2: fused dual GEMM + bias
    static int smem_set = 0;
    const int smem_bytes = 2 * (BM + BN) * SSTR * sizeof(float);   // 73728
    if (!smem_set) {
        cudaFuncSetAttribute(gemm_kernel, cudaFuncAttributeMaxDynamicSharedMemorySize, smem_bytes);
        smem_set = 1;
    }
    dim3 grid(OUT_DIM / BN, (N + BM - 1) / BM);   // (4, 157)
    gemm_kernel<<<grid, NTHREADS, smem_bytes>>>(x, Wl, Wr, bl, br, out, N);
}

// round 3
// speedup vs baseline: 1.0296x; 1.0296x over previous
#include <cuda_runtime.h>
#include <cstdint>

// Problem constants (shape-fixed: N=20000, K=32, C=512, OUT=512)
#define C_DIM   512
#define OUT_DIM 512
#define K_NB    32
#define N_MAX   20000

// GEMM tiling: block 128x256, 8 warps of 64x64, BK=32, 3-stage cp.async
#define BM       128
#define BN       256
#define BK       32
#define SSTR     36                      // padded smem row stride (words)
#define NSTAGE   3
#define THREADS  256
#define A_WORDS  (BM * SSTR)             // 4608
#define B_WORDS  (BN * SSTR)             // 9216
#define STG_WORDS (A_WORDS + B_WORDS)    // 13824
#define SMEM_WORDS (NSTAGE * STG_WORDS + OUT_DIM + 16)
#define SMEM_BYTES (SMEM_WORDS * 4)      // ~168 KB

// tf32-bit scratch (u32 payloads fed raw to mma.sync)
__device__ uint32_t g_agg[(size_t)N_MAX * C_DIM];
__device__ uint32_t g_x  [(size_t)N_MAX * C_DIM];
__device__ uint32_t g_wl [OUT_DIM * C_DIM];
__device__ uint32_t g_wr [OUT_DIM * C_DIM];

__device__ __forceinline__ uint32_t f2tf32(float f) {
    uint32_t r;
    asm("cvt.rna.tf32.f32 %0, %1;" : "=r"(r) : "f"(f));
    return r;
}

// ---------------------------------------------------------------------------
// Prep kernel: [0,N)      : mean over K_NB + tf32 convert  -> g_agg
//              [N,N+NX)   : convert x                      -> g_x
//              [N+NX,+512): convert Wl, Wr                 -> g_wl, g_wr
// ---------------------------------------------------------------------------
__global__ void __launch_bounds__(128) prep_kernel(
    const float* __restrict__ nx, const float* __restrict__ x,
    const float* __restrict__ wl, const float* __restrict__ wr, int N)
{
    const int bid = blockIdx.x;
    const int tid = threadIdx.x;

    if (bid < N) {
        // mean over neighbor axis for node bid
        const float4* p = reinterpret_cast<const float4*>(nx + (size_t)bid * K_NB * C_DIM) + tid;
        float4 s = make_float4(0.f, 0.f, 0.f, 0.f);
#pragma unroll 8
        for (int k = 0; k < K_NB; ++k) {
            float4 v = p[(size_t)k * (C_DIM / 4)];
            s.x += v.x; s.y += v.y; s.z += v.z; s.w += v.w;
        }
        const float inv = 1.0f / (float)K_NB;
        uint4 o;
        o.x = f2tf32(s.x * inv); o.y = f2tf32(s.y * inv);
        o.z = f2tf32(s.z * inv); o.w = f2tf32(s.w * inv);
        reinterpret_cast<uint4*>(g_agg + (size_t)bid * C_DIM)[tid] = o;
    } else if (bid < N + (N / 8)) {                 // NX = N*128/1024 = N/8 blocks
        const int i = bid - N;
        const float4* src = reinterpret_cast<const float4*>(x);
        uint4* dst = reinterpret_cast<uint4*>(g_x);
#pragma unroll
        for (int j = 0; j < 8; ++j) {
            size_t idx = (size_t)i * 1024 + j * 128 + tid;
            float4 v = src[idx];
            uint4 o;
            o.x = f2tf32(v.x); o.y = f2tf32(v.y); o.z = f2tf32(v.z); o.w = f2tf32(v.w);
            dst[idx] = o;
        }
    } else {
        const int i = bid - N - (N / 8);            // 0..511
        const bool isL = (i < 256);
        const float4* src = reinterpret_cast<const float4*>(isL ? wl : wr);
        uint4* dst = reinterpret_cast<uint4*>(isL ? g_wl : g_wr);
        const int mb = isL ? i : i - 256;
#pragma unroll
        for (int j = 0; j < 2; ++j) {
            size_t idx = (size_t)mb * 256 + j * 128 + tid;
            float4 v = src[idx];
            uint4 o;
            o.x = f2tf32(v.x); o.y = f2tf32(v.y); o.z = f2tf32(v.z); o.w = f2tf32(v.w);
            dst[idx] = o;
        }
    }
}

// ---------------------------------------------------------------------------
// GEMM helpers
// ---------------------------------------------------------------------------
__device__ __forceinline__ void mma_tf32(float* c, const uint32_t* a, const uint32_t* b) {
    asm volatile(
        "mma.sync.aligned.m16n8k8.row.col.f32.tf32.tf32.f32 "
        "{%0,%1,%2,%3}, {%4,%5,%6,%7}, {%8,%9}, {%0,%1,%2,%3};"
        : "+f"(c[0]), "+f"(c[1]), "+f"(c[2]), "+f"(c[3])
        : "r"(a[0]), "r"(a[1]), "r"(a[2]), "r"(a[3]), "r"(b[0]), "r"(b[1]));
}

__device__ __forceinline__ void cp_async16(uint32_t saddr, const void* gsrc, int src_bytes) {
    asm volatile("cp.async.cg.shared.global [%0], [%1], 16, %2;\n"
                 :: "r"(saddr), "l"(gsrc), "r"(src_bytes));
}

// ---------------------------------------------------------------------------
// GEMM: out = x@Wl^T + agg@Wr^T + (bl+br), tf32 mma.sync, all operands
// pre-converted. Grid = 157 row-blocks; each sweeps bx = 0,1 column halves.
// ---------------------------------------------------------------------------
__global__ void __launch_bounds__(THREADS, 1)
gemm_kernel(const float* __restrict__ bl, const float* __restrict__ br,
            float* __restrict__ out, int Nrows)
{
    extern __shared__ uint32_t smem[];
    uint32_t* stages = smem;                              // NSTAGE * STG_WORDS
    float*    bias   = reinterpret_cast<float*>(smem + NSTAGE * STG_WORDS);
    const uint32_t smem_u32 = (uint32_t)__cvta_generic_to_shared(smem);

    const int tid  = threadIdx.x;
    const int lane = tid & 31;
    const int warp = tid >> 5;
    const int wm   = warp & 1;                 // 2 row groups of 64
    const int wn   = warp >> 1;                // 4 col groups of 64
    const int rowBase = blockIdx.x * BM;

    for (int i = tid; i < OUT_DIM; i += THREADS) bias[i] = bl[i] + br[i];
    __syncthreads();

    // precomputed per-thread fragment smem offsets (words)
    const int a_r = wm * 64 + (lane >> 2);     // + mt*16 (+8)
    const int fc  = lane & 3;
    const int b_o = wn * 64 + (lane >> 2);     // + nt*8

    for (int bx = 0; bx < 2; ++bx) {
        float acc[4][8][4];
#pragma unroll
        for (int mt = 0; mt < 4; ++mt)
#pragma unroll
            for (int nt = 0; nt < 8; ++nt)
#pragma unroll
                for (int i = 0; i < 4; ++i) acc[mt][nt][i] = 0.f;

        // ---- chunk loader ----
        auto issue = [&](int ch) {
            const int s = ch % NSTAGE;
            const uint32_t sa = smem_u32 + (s * STG_WORDS) * 4;
            const uint32_t sb = sa + A_WORDS * 4;
            const uint32_t* Ap = (ch < 16) ? g_x  : g_agg;
            const uint32_t* Bp = (ch < 16) ? g_wl : g_wr;
            const int kk = (ch & 15) * BK;
#pragma unroll
            for (int i = 0; i < 4; ++i) {                 // A: 128 x 32
                int idx = i * THREADS + tid;              // 0..1023
                int r = idx >> 3, c4 = (idx & 7) * 4;
                int grow = rowBase + r;
                cp_async16(sa + (r * SSTR + c4) * 4,
                           Ap + (size_t)grow * C_DIM + kk + c4,
                           (grow < Nrows) ? 16 : 0);
            }
#pragma unroll
            for (int i = 0; i < 8; ++i) {                 // B: 256 x 32
                int idx = i * THREADS + tid;              // 0..2047
                int o = idx >> 3, c4 = (idx & 7) * 4;
                cp_async16(sb + (o * SSTR + c4) * 4,
                           Bp + (size_t)(bx * BN + o) * C_DIM + kk + c4, 16);
            }
            asm volatile("cp.async.commit_group;\n");
        };

        issue(0); issue(1);
        for (int t = 0; t < 32; ++t) {
            const int lc = t + 2;
            if (lc < 32) {
                issue(lc);
                asm volatile("cp.async.wait_group 2;\n");
            } else if (lc == 32) {
                asm volatile("cp.async.wait_group 1;\n");
            } else {
                asm volatile("cp.async.wait_group 0;\n");
            }
            __syncthreads();

            const uint32_t* as = stages + (t % NSTAGE) * STG_WORDS;
            const uint32_t* bs = as + A_WORDS;
#pragma unroll
            for (int ks = 0; ks < 4; ++ks) {
                const int kb = ks * 8;
                uint32_t afr[4][4];
#pragma unroll
                for (int mt = 0; mt < 4; ++mt) {
                    const int r = a_r + mt * 16;
                    afr[mt][0] = as[r * SSTR + kb + fc];
                    afr[mt][1] = as[(r + 8) * SSTR + kb + fc];
                    afr[mt][2] = as[r * SSTR + kb + fc + 4];
                    afr[mt][3] = as[(r + 8) * SSTR + kb + fc + 4];
                }
                uint32_t bfr[8][2];
#pragma unroll
                for (int nt = 0; nt < 8; ++nt) {
                    const int o = b_o + nt * 8;
                    bfr[nt][0] = bs[o * SSTR + kb + fc];
                    bfr[nt][1] = bs[o * SSTR + kb + fc + 4];
                }
#pragma unroll
                for (int mt = 0; mt < 4; ++mt)
#pragma unroll
                    for (int nt = 0; nt < 8; ++nt)
                        mma_tf32(acc[mt][nt], afr[mt], bfr[nt]);
            }
            __syncthreads();
        }

        // ---- epilogue ----
#pragma unroll
        for (int nt = 0; nt < 8; ++nt) {
            const int col  = bx * BN + wn * 64 + nt * 8 + 2 * (lane & 3);
            const float b0 = bias[col], b1 = bias[col + 1];
#pragma unroll
            for (int mt = 0; mt < 4; ++mt) {
                const int row0 = rowBase + wm * 64 + mt * 16 + (lane >> 2);
                const int row1 = row0 + 8;
                if (row0 < Nrows) {
                    float2 v = make_float2(acc[mt][nt][0] + b0, acc[mt][nt][1] + b1);
                    *reinterpret_cast<float2*>(out + (size_t)row0 * OUT_DIM + col) = v;
                }
                if (row1 < Nrows) {
                    float2 v = make_float2(acc[mt][nt][2] + b0, acc[mt][nt][3] + b1);
                    *reinterpret_cast<float2*>(out + (size_t)row1 * OUT_DIM + col) = v;
                }
            }
        }
        __syncthreads();   // protect stage smem before next bx reuses it
    }
}

// ---------------------------------------------------------------------------
// Launch
// ---------------------------------------------------------------------------
extern "C" void kernel_launch(void* const* d_in, const int* in_sizes, int n_in,
                              void* d_out, int out_size)
{
    const float* x     = (const float*)d_in[0];
    const float* neigh = (const float*)d_in[1];
    const float* Wl    = (const float*)d_in[2];
    const float* bl    = (const float*)d_in[3];
    const float* Wr    = (const float*)d_in[4];
    const float* br    = (const float*)d_in[5];
    float* out = (float*)d_out;

    const int N = in_sizes[0] / C_DIM;        // 20000

    // Prep: mean+cvt (N blocks) + x cvt (N/8 blocks) + W cvt (512 blocks)
    const int prep_blocks = N + (N / 8) + 512;
    prep_kernel<<<prep_blocks, 128>>>(neigh, x, Wl, Wr, N);

    static int smem_set = 0;
    if (!smem_set) {
        cudaFuncSetAttribute(gemm_kernel, cudaFuncAttributeMaxDynamicSharedMemorySize, SMEM_BYTES);
        smem_set = 1;
    }
    gemm_kernel<<<(N + BM - 1) / BM, THREADS, SMEM_BYTES>>>(bl, br, out, N);
}